// round 16
// baseline (speedup 1.0000x reference)
#include <cuda_runtime.h>
#include <cuda_fp16.h>
#include <cstdint>

// Problem constants
#define BB 16
#define NN 12800
#define FM 128          // F_MSG
#define FN 256          // F_NODE
#define NBINS 100       // N / BIN_SIZE
#define HB 50           // NBINS / 2
#define BS 128          // BIN_SIZE
#define NKEYS 200       // bin keys in [0, 198]
#define ROTC 100        // rot second-dim stride (MAX_NUM_BINS/2)

// Output layout (flattened float32, reference tuple order)
#define OFF_BINS   0
#define LEN_BINS   (BB * NN)                  // 204800
#define OFF_XNODE  (OFF_BINS + LEN_BINS)      // 204800
#define LEN_XNODE  (BB * NN * FN)             // 52428800
#define OFF_DM     (OFF_XNODE + LEN_XNODE)    // 52633600
#define LEN_DM     (BB * NN * BS)             // 26214400
#define OFF_MSKF   (OFF_DM + LEN_DM)          // 78848000

// Scratch (device globals: no allocation allowed)
__device__ int g_key[BB * NN];    // bin key per (b,n)
__device__ int g_bins[BB * NN];   // sorted original indices (bins_split)

typedef unsigned long long u64;

__device__ __forceinline__ float ex2f(float x) {
    float y; asm("ex2.approx.f32 %0, %1;" : "=f"(y) : "f"(x)); return y;
}
__device__ __forceinline__ float rsqf(float x) {
    float y; asm("rsqrt.approx.f32 %0, %1;" : "=f"(y) : "f"(x)); return y;
}

// ---------------------------------------------------------------------------
// K1: LSH projection via fp16 mma.sync + exact fp32 fallback.
// occ 4 (64-reg cap; live set ~58): 32 warps/SM on a DRAM-latency kernel.
// ---------------------------------------------------------------------------
#define STH 136
#define PROJ_TH 3e-3f
__global__ void __launch_bounds__(256, 4)
k_proj(const float* __restrict__ x_msg,
       const int* __restrict__ msk,
       const float* __restrict__ rot) {
    const int b  = blockIdx.x / (NN / 128);
    const int n0 = (blockIdx.x % (NN / 128)) * 128;
    extern __shared__ char smp[];
    __half* Xh = (__half*)smp;                          // [128][STH]
    __half* Rh = (__half*)(smp + 128 * STH * 2);        // [64][STH]
    int* scnt  = (int*)(smp + 128 * STH * 2 + 64 * STH * 2);
    int* slist = scnt + 1;                              // [128]
    const int tid  = threadIdx.x;    // 256
    const int w    = tid >> 5;       // 0..7
    const int lane = tid & 31;

    if (tid == 0) *scnt = 0;

    // Stage Xh: warp w rows w*16..+15; lane owns 16B chunk (4 floats).
    {
        const float4* xr = (const float4*)(x_msg + ((size_t)b * NN + n0) * FM);
#pragma unroll
        for (int rr = 0; rr < 16; rr++) {
            const int r = w * 16 + rr;
            float4 v = xr[(size_t)r * (FM / 4) + lane];
            *(__half2*)(Xh + r * STH + lane * 4)     = __floats2half2_rn(v.x, v.y);
            *(__half2*)(Xh + r * STH + lane * 4 + 2) = __floats2half2_rn(v.z, v.w);
        }
    }
    // Stage Rh[h][f] = rot[f][h] (fp16), h in [50,64) zero.
    for (int idx = tid; idx < 64 * 64; idx += 256) {
        const int h  = idx >> 6;
        const int f2 = idx & 63;
        float v0 = 0.f, v1 = 0.f;
        if (h < HB) {
            v0 = rot[(2 * f2) * ROTC + h];
            v1 = rot[(2 * f2 + 1) * ROTC + h];
        }
        *(__half2*)(Rh + h * STH + 2 * f2) = __floats2half2_rn(v0, v1);
    }
    __syncthreads();

    // MMA: warp w -> rows i0 = w*16, all 64 cols.
    const int i0 = w * 16;
    const uint32_t xBase = (uint32_t)__cvta_generic_to_shared(Xh);
    const uint32_t rBase = (uint32_t)__cvta_generic_to_shared(Rh);
    float cacc[8][4];
#pragma unroll
    for (int t = 0; t < 8; t++)
#pragma unroll
        for (int e = 0; e < 4; e++) cacc[t][e] = 0.f;

    for (int k = 0; k < 8; k++) {
        const int k0 = k * 16;
        uint32_t a0, a1, a2, a3;
        {
            uint32_t aaddr = xBase +
                (((i0 + (lane & 15)) * STH + k0 + ((lane >> 4) << 3)) << 1);
            asm volatile(
                "ldmatrix.sync.aligned.m8n8.x4.shared.b16 {%0,%1,%2,%3}, [%4];"
                : "=r"(a0), "=r"(a1), "=r"(a2), "=r"(a3) : "r"(aaddr));
        }
#pragma unroll
        for (int p = 0; p < 4; p++) {
            const int j0 = p * 16;
            uint32_t b0, b1, b2, b3;
            uint32_t row = j0 + (lane & 7) + ((lane >> 4) << 3);
            uint32_t col = k0 + (((lane >> 3) & 1) << 3);
            uint32_t baddr = rBase + ((row * STH + col) << 1);
            asm volatile(
                "ldmatrix.sync.aligned.m8n8.x4.shared.b16 {%0,%1,%2,%3}, [%4];"
                : "=r"(b0), "=r"(b1), "=r"(b2), "=r"(b3) : "r"(baddr));
            asm volatile(
                "mma.sync.aligned.m16n8k16.row.col.f32.f16.f16.f32 "
                "{%0,%1,%2,%3}, {%4,%5,%6,%7}, {%8,%9}, {%0,%1,%2,%3};"
                : "+f"(cacc[2 * p][0]), "+f"(cacc[2 * p][1]),
                  "+f"(cacc[2 * p][2]), "+f"(cacc[2 * p][3])
                : "r"(a0), "r"(a1), "r"(a2), "r"(a3), "r"(b0), "r"(b1));
            asm volatile(
                "mma.sync.aligned.m16n8k16.row.col.f32.f16.f16.f32 "
                "{%0,%1,%2,%3}, {%4,%5,%6,%7}, {%8,%9}, {%0,%1,%2,%3};"
                : "+f"(cacc[2 * p + 1][0]), "+f"(cacc[2 * p + 1][1]),
                  "+f"(cacc[2 * p + 1][2]), "+f"(cacc[2 * p + 1][3])
                : "r"(a0), "r"(a1), "r"(a2), "r"(a3), "r"(b2), "r"(b3));
        }
    }

    // Per-row argmax/argmin with top-2 tracking; rows r0, r1 sequentially.
#pragma unroll
    for (int half = 0; half < 2; half++) {
        const int r = i0 + (lane >> 2) + half * 8;
        float bm1 = -3.4e38f, bm2 = -3.4e38f; int bi1 = 9999;
        float sm1 =  3.4e38f, sm2 =  3.4e38f; int si1 = 9999;
#pragma unroll
        for (int t = 0; t < 8; t++) {
            const int hcol = t * 8 + (lane & 3) * 2;
#pragma unroll
            for (int e = 0; e < 2; e++) {
                float v = cacc[t][half * 2 + e];
                int   h = hcol + e;
                if (v > bm1) { bm2 = bm1; bm1 = v; bi1 = h; }
                else bm2 = fmaxf(bm2, v);
                if (v < sm1) { sm2 = sm1; sm1 = v; si1 = h; }
                else sm2 = fminf(sm2, v);
            }
        }
        // reduce across the 4 lanes sharing this row (xor 1, 2)
#pragma unroll
        for (int off = 1; off <= 2; off <<= 1) {
            float obm1 = __shfl_xor_sync(0xffffffffu, bm1, off);
            int   obi1 = __shfl_xor_sync(0xffffffffu, bi1, off);
            float obm2 = __shfl_xor_sync(0xffffffffu, bm2, off);
            float osm1 = __shfl_xor_sync(0xffffffffu, sm1, off);
            int   osi1 = __shfl_xor_sync(0xffffffffu, si1, off);
            float osm2 = __shfl_xor_sync(0xffffffffu, sm2, off);
            if (obm1 > bm1 || (obm1 == bm1 && obi1 < bi1)) {
                bm2 = fmaxf(bm1, obm2); bm1 = obm1; bi1 = obi1;
            } else bm2 = fmaxf(bm2, obm1);
            if (osm1 < sm1 || (osm1 == sm1 && osi1 < si1)) {
                sm2 = fminf(sm1, osm2); sm1 = osm1; si1 = osi1;
            } else sm2 = fminf(sm2, osm1);
        }
        if ((lane & 3) == 0) {
            const float gapb = bm1 - bm2;
            const float gapm = sm2 - sm1;
            const float marg = fabsf(bm1 + sm1);   // |bv - (-mv)|
            const int n = n0 + r;
            if (gapb > PROJ_TH && gapm > PROJ_TH && marg > PROJ_TH) {
                int idx = (bm1 >= -sm1) ? bi1 : (HB + si1);
                int m = msk[(size_t)b * NN + n];
                g_key[(size_t)b * NN + n] = idx + (m ? 0 : (NBINS - 1));
            } else {
                int pos = atomicAdd(scnt, 1);
                slist[pos] = r;
            }
        }
    }
    __syncthreads();

    // Exact fp32 recompute for flagged nodes (one warp per node).
    const int cnt = *scnt;
    for (int ii = w; ii < cnt; ii += 8) {
        const int r = slist[ii];
        const int h0 = lane;
        const int h1 = lane + 32;
        const bool v1ok = (h1 < HB);
        float d0 = 0.f, d1 = 0.f;
        const float4* xr4 = (const float4*)(x_msg + ((size_t)b * NN + n0 + r) * FM);
        for (int f4 = 0; f4 < FM / 4; f4++) {
            float4 xv = __ldg(xr4 + f4);
            const float* rp = rot + (4 * f4) * ROTC;
            d0 = fmaf(xv.x, __ldg(rp + h0), d0);
            d0 = fmaf(xv.y, __ldg(rp + ROTC + h0), d0);
            d0 = fmaf(xv.z, __ldg(rp + 2 * ROTC + h0), d0);
            d0 = fmaf(xv.w, __ldg(rp + 3 * ROTC + h0), d0);
            if (v1ok) {
                d1 = fmaf(xv.x, __ldg(rp + h1), d1);
                d1 = fmaf(xv.y, __ldg(rp + ROTC + h1), d1);
                d1 = fmaf(xv.z, __ldg(rp + 2 * ROTC + h1), d1);
                d1 = fmaf(xv.w, __ldg(rp + 3 * ROTC + h1), d1);
            }
        }
        float bv = d0; int bh = h0;
        if (v1ok && d1 > bv) { bv = d1; bh = h1; }
        float mv = d0; int mh = h0;
        if (v1ok && d1 < mv) { mv = d1; mh = h1; }
#pragma unroll
        for (int off = 16; off; off >>= 1) {
            float obv = __shfl_xor_sync(0xffffffffu, bv, off);
            int   obh = __shfl_xor_sync(0xffffffffu, bh, off);
            float omv = __shfl_xor_sync(0xffffffffu, mv, off);
            int   omh = __shfl_xor_sync(0xffffffffu, mh, off);
            if (obv > bv || (obv == bv && obh < bh)) { bv = obv; bh = obh; }
            if (omv < mv || (omv == mv && omh < mh)) { mv = omv; mh = omh; }
        }
        if (lane == 0) {
            const int n = n0 + r;
            int idx = (bv >= -mv) ? bh : (HB + mh);
            int m = msk[(size_t)b * NN + n];
            g_key[(size_t)b * NN + n] = idx + (m ? 0 : (NBINS - 1));
        }
    }
}

// ---------------------------------------------------------------------------
// K2: stable counting sort per batch (unchanged).
// ---------------------------------------------------------------------------
__global__ void k_sort(const int* __restrict__ msk,
                       float* __restrict__ out) {
    const int b = blockIdx.x;
    extern __shared__ unsigned short off[];        // [NKEYS][128]
    __shared__ unsigned int keyTotal[NKEYS];
    __shared__ unsigned int keyBase[NKEYS];
    const int t = threadIdx.x;

    for (int i = t; i < NKEYS * 128; i += 128) off[i] = 0;
    __syncthreads();

    const int* kb = g_key + (size_t)b * NN;
    const int base_n = t * 100;
    for (int q = 0; q < 100; q++) {
        int k = kb[base_n + q];
        off[k * 128 + t]++;
    }
    __syncthreads();

    for (int k = t; k < NKEYS; k += 128) {
        unsigned int run = 0;
        for (int tt = 0; tt < 128; tt++) {
            unsigned short c = off[k * 128 + tt];
            off[k * 128 + tt] = (unsigned short)run;
            run += c;
        }
        keyTotal[k] = run;
    }
    __syncthreads();
    if (t == 0) {
        unsigned int run = 0;
        for (int k = 0; k < NKEYS; k++) { keyBase[k] = run; run += keyTotal[k]; }
    }
    __syncthreads();

    int* gb = g_bins + (size_t)b * NN;
    const int* mb = msk + (size_t)b * NN;
    float* out_bins = out + OFF_BINS + (size_t)b * NN;
    float* out_mskf = out + OFF_MSKF + (size_t)b * NN;
    for (int q = 0; q < 100; q++) {
        int n = base_n + q;
        int k = kb[n];
        unsigned int pos = keyBase[k] + off[k * 128 + t];
        off[k * 128 + t]++;
        gb[pos] = n;
        out_bins[pos] = (float)n;
        out_mskf[pos] = mb[n] ? 1.0f : 0.0f;
    }
}

// ---------------------------------------------------------------------------
// K4: per-bin gaussian kernel via tensor-core mma.sync + fused x_node gather.
// v2: batched staging loads (MLP 8), 2-row batched gather with streaming
// ld/st (4 float4 in flight), streaming dm writes. Arithmetic unchanged.
// 512 thr x occ 2 = 32 warps/SM (hardware warp max).
// ---------------------------------------------------------------------------
__global__ void __launch_bounds__(512, 2)
k_dm(const float4* __restrict__ x_msg4,
     const int* __restrict__ msk,
     const float4* __restrict__ x_node4,
     float* __restrict__ out) {
    const int b   = blockIdx.x / NBINS;
    const int bin = blockIdx.x % NBINS;
    extern __shared__ char smraw[];
    __half* As = (__half*)smraw;                       // [128][STH]
    float* na  = (float*)(smraw + 128 * STH * 2);      // [128]
    float* mm  = na + 128;                             // [128]
    const int tid  = threadIdx.x;        // 512
    const int w    = tid >> 5;           // 0..15
    const int lane = tid & 31;

    const int* gb = g_bins + ((size_t)b * NBINS + bin) * BS;
    const float4* xb = x_msg4 + (size_t)b * NN * (FM / 4);

    // Staging with batched loads: issue all 8 row loads first (MLP 8).
    {
        float4 vv[8];
        float  mk[8];
#pragma unroll
        for (int rr = 0; rr < 8; rr++) {
            const int r = w * 8 + rr;
            const int src = gb[r];                    // warp-uniform broadcast
            mk[rr] = msk[(size_t)b * NN + src] ? 1.f : 0.f;
            vv[rr] = xb[(size_t)src * (FM / 4) + lane];
        }
#pragma unroll
        for (int rr = 0; rr < 8; rr++) {
            const int r = w * 8 + rr;
            const float m = mk[rr];
            float4 v = vv[rr];
            v.x *= m; v.y *= m; v.z *= m; v.w *= m;
            __half2 h0 = __floats2half2_rn(v.x, v.y);
            __half2 h1 = __floats2half2_rn(v.z, v.w);
            *(__half2*)(As + r * STH + lane * 4)     = h0;
            *(__half2*)(As + r * STH + lane * 4 + 2) = h1;
            float2 f0 = __half22float2(h0), f1 = __half22float2(h1);
            float s = f0.x * f0.x + f0.y * f0.y + f1.x * f1.x + f1.y * f1.y;
#pragma unroll
            for (int o = 16; o; o >>= 1) s += __shfl_xor_sync(0xffffffffu, s, o);
            if (lane == 0) { na[r] = s; mm[r] = m; }
        }
    }
    __syncthreads();

    const int i0  = (w & 7) * 16;
    const int j0c = (w >> 3) * 64;
    const uint32_t asBase = (uint32_t)__cvta_generic_to_shared(As);

    float cacc[8][4];
#pragma unroll
    for (int t = 0; t < 8; t++)
#pragma unroll
        for (int e = 0; e < 4; e++) cacc[t][e] = 0.f;

    for (int k = 0; k < 8; k++) {
        const int k0 = k * 16;
        uint32_t a0, a1, a2, a3;
        {
            uint32_t aaddr = asBase +
                (((i0 + (lane & 15)) * STH + k0 + ((lane >> 4) << 3)) << 1);
            asm volatile(
                "ldmatrix.sync.aligned.m8n8.x4.shared.b16 {%0,%1,%2,%3}, [%4];"
                : "=r"(a0), "=r"(a1), "=r"(a2), "=r"(a3) : "r"(aaddr));
        }
#pragma unroll
        for (int p = 0; p < 4; p++) {
            const int j0 = j0c + p * 16;
            uint32_t b0, b1, b2, b3;
            uint32_t row = j0 + (lane & 7) + ((lane >> 4) << 3);
            uint32_t col = k0 + (((lane >> 3) & 1) << 3);
            uint32_t baddr = asBase + ((row * STH + col) << 1);
            asm volatile(
                "ldmatrix.sync.aligned.m8n8.x4.shared.b16 {%0,%1,%2,%3}, [%4];"
                : "=r"(b0), "=r"(b1), "=r"(b2), "=r"(b3) : "r"(baddr));
            asm volatile(
                "mma.sync.aligned.m16n8k16.row.col.f32.f16.f16.f32 "
                "{%0,%1,%2,%3}, {%4,%5,%6,%7}, {%8,%9}, {%0,%1,%2,%3};"
                : "+f"(cacc[2 * p][0]), "+f"(cacc[2 * p][1]),
                  "+f"(cacc[2 * p][2]), "+f"(cacc[2 * p][3])
                : "r"(a0), "r"(a1), "r"(a2), "r"(a3), "r"(b0), "r"(b1));
            asm volatile(
                "mma.sync.aligned.m16n8k16.row.col.f32.f16.f16.f32 "
                "{%0,%1,%2,%3}, {%4,%5,%6,%7}, {%8,%9}, {%0,%1,%2,%3};"
                : "+f"(cacc[2 * p + 1][0]), "+f"(cacc[2 * p + 1][1]),
                  "+f"(cacc[2 * p + 1][2]), "+f"(cacc[2 * p + 1][3])
                : "r"(a0), "r"(a1), "r"(a2), "r"(a3), "r"(b2), "r"(b3));
        }
    }

    {
        float* dout = out + OFF_DM + (size_t)blockIdx.x * BS * BS;
        const float cst = -0.14426950408889634f;   // -DIST_MULT * log2(e)
        const int r0 = i0 + (lane >> 2);
        const int r1 = r0 + 8;
        const float na0 = na[r0], m0 = mm[r0];
        const float na1 = na[r1], m1 = mm[r1];
#pragma unroll
        for (int t = 0; t < 8; t++) {
            const int j = j0c + t * 8 + (lane & 3) * 2;
            const float naj0 = na[j], mj0 = mm[j];
            const float naj1 = na[j + 1], mj1 = mm[j + 1];
            float x, d;
            x = fmaxf(na0 + naj0 - 2.0f * cacc[t][0], 1e-6f);
            d = fminf(ex2f(cst * (x * rsqf(x))) * m0 * mj0, 1.0f);
            float e0 = d;
            x = fmaxf(na0 + naj1 - 2.0f * cacc[t][1], 1e-6f);
            d = fminf(ex2f(cst * (x * rsqf(x))) * m0 * mj1, 1.0f);
            float e1 = d;
            x = fmaxf(na1 + naj0 - 2.0f * cacc[t][2], 1e-6f);
            d = fminf(ex2f(cst * (x * rsqf(x))) * m1 * mj0, 1.0f);
            float e2 = d;
            x = fmaxf(na1 + naj1 - 2.0f * cacc[t][3], 1e-6f);
            d = fminf(ex2f(cst * (x * rsqf(x))) * m1 * mj1, 1.0f);
            float e3 = d;
            __stcs((float2*)(dout + (size_t)r0 * BS + j), make_float2(e0, e1));
            __stcs((float2*)(dout + (size_t)r1 * BS + j), make_float2(e2, e3));
        }
    }

    // Fused x_node gather: 2-row batches, streaming ld/st (4 float4 in flight).
    const float4* xn = x_node4 + (size_t)b * NN * (FN / 4);
    float4* xo = (float4*)(out + OFF_XNODE) + (size_t)blockIdx.x * BS * (FN / 4);
#pragma unroll
    for (int it = 0; it < 4; it++) {
        const int r0 = w + it * 32;
        const int r1 = r0 + 16;
        const int s0 = gb[r0];
        const int s1 = gb[r1];
        float4 a0 = __ldcs(xn + (size_t)s0 * 64 + lane);
        float4 a1 = __ldcs(xn + (size_t)s0 * 64 + lane + 32);
        float4 b0 = __ldcs(xn + (size_t)s1 * 64 + lane);
        float4 b1 = __ldcs(xn + (size_t)s1 * 64 + lane + 32);
        __stcs(xo + (size_t)r0 * 64 + lane,      a0);
        __stcs(xo + (size_t)r0 * 64 + lane + 32, a1);
        __stcs(xo + (size_t)r1 * 64 + lane,      b0);
        __stcs(xo + (size_t)r1 * 64 + lane + 32, b1);
    }
}

// ---------------------------------------------------------------------------
extern "C" void kernel_launch(void* const* d_in, const int* in_sizes, int n_in,
                              void* d_out, int out_size) {
    const float* x_msg  = (const float*)d_in[0];
    const float* x_node = (const float*)d_in[1];
    const int*   msk    = (const int*)d_in[2];
    const float* rot    = (const float*)d_in[3];
    float* out = (float*)d_out;

    const int SM1 = 128 * STH * 2 + 64 * STH * 2 + 4 + 128 * 4;  // 52740
    const int SM2 = NKEYS * 128 * 2;                    // 51200
    const int SM4 = 128 * STH * 2 + 2 * 128 * 4;        // 35840
    cudaFuncSetAttribute(k_proj, cudaFuncAttributeMaxDynamicSharedMemorySize, SM1);
    cudaFuncSetAttribute(k_sort, cudaFuncAttributeMaxDynamicSharedMemorySize, SM2);
    cudaFuncSetAttribute(k_dm,   cudaFuncAttributeMaxDynamicSharedMemorySize, SM4);

    k_proj<<<BB * (NN / 128), 256, SM1>>>(x_msg, msk, rot);
    k_sort<<<BB, 128, SM2>>>(msk, out);
    k_dm<<<BB * NBINS, 512, SM4>>>((const float4*)x_msg, msk,
                                   (const float4*)x_node, out);
}

// round 17
// speedup vs baseline: 1.1472x; 1.1472x over previous
#include <cuda_runtime.h>
#include <cuda_fp16.h>
#include <cstdint>

// Problem constants
#define BB 16
#define NN 12800
#define FM 128          // F_MSG
#define FN 256          // F_NODE
#define NBINS 100       // N / BIN_SIZE
#define HB 50           // NBINS / 2
#define BS 128          // BIN_SIZE
#define NKEYS 200       // bin keys in [0, 198]
#define ROTC 100        // rot second-dim stride (MAX_NUM_BINS/2)

// Output layout (flattened float32, reference tuple order)
#define OFF_BINS   0
#define LEN_BINS   (BB * NN)                  // 204800
#define OFF_XNODE  (OFF_BINS + LEN_BINS)      // 204800
#define LEN_XNODE  (BB * NN * FN)             // 52428800
#define OFF_DM     (OFF_XNODE + LEN_XNODE)    // 52633600
#define LEN_DM     (BB * NN * BS)             // 26214400
#define OFF_MSKF   (OFF_DM + LEN_DM)          // 78848000

// Scratch (device globals: no allocation allowed)
__device__ int g_key[BB * NN];    // bin key per (b,n)
__device__ int g_bins[BB * NN];   // sorted original indices (bins_split)

typedef unsigned long long u64;

__device__ __forceinline__ float ex2f(float x) {
    float y; asm("ex2.approx.f32 %0, %1;" : "=f"(y) : "f"(x)); return y;
}
__device__ __forceinline__ float rsqf(float x) {
    float y; asm("rsqrt.approx.f32 %0, %1;" : "=f"(y) : "f"(x)); return y;
}

// ---------------------------------------------------------------------------
// K1: LSH projection via fp16 mma.sync + exact fp32 fallback.
// occ 3 (natural regs ~80; occ-4/64-reg cap PROVEN to spill in R16: 60->90us).
// ---------------------------------------------------------------------------
#define STH 136
#define PROJ_TH 3e-3f
__global__ void __launch_bounds__(256, 3)
k_proj(const float* __restrict__ x_msg,
       const int* __restrict__ msk,
       const float* __restrict__ rot) {
    const int b  = blockIdx.x / (NN / 128);
    const int n0 = (blockIdx.x % (NN / 128)) * 128;
    extern __shared__ char smp[];
    __half* Xh = (__half*)smp;                          // [128][STH]
    __half* Rh = (__half*)(smp + 128 * STH * 2);        // [64][STH]
    int* scnt  = (int*)(smp + 128 * STH * 2 + 64 * STH * 2);
    int* slist = scnt + 1;                              // [128]
    const int tid  = threadIdx.x;    // 256
    const int w    = tid >> 5;       // 0..7
    const int lane = tid & 31;

    if (tid == 0) *scnt = 0;

    // Stage Xh: warp w rows w*16..+15; lane owns 16B chunk (4 floats).
    {
        const float4* xr = (const float4*)(x_msg + ((size_t)b * NN + n0) * FM);
#pragma unroll
        for (int rr = 0; rr < 16; rr++) {
            const int r = w * 16 + rr;
            float4 v = xr[(size_t)r * (FM / 4) + lane];
            *(__half2*)(Xh + r * STH + lane * 4)     = __floats2half2_rn(v.x, v.y);
            *(__half2*)(Xh + r * STH + lane * 4 + 2) = __floats2half2_rn(v.z, v.w);
        }
    }
    // Stage Rh[h][f] = rot[f][h] (fp16), h in [50,64) zero.
    for (int idx = tid; idx < 64 * 64; idx += 256) {
        const int h  = idx >> 6;
        const int f2 = idx & 63;
        float v0 = 0.f, v1 = 0.f;
        if (h < HB) {
            v0 = rot[(2 * f2) * ROTC + h];
            v1 = rot[(2 * f2 + 1) * ROTC + h];
        }
        *(__half2*)(Rh + h * STH + 2 * f2) = __floats2half2_rn(v0, v1);
    }
    __syncthreads();

    // MMA: warp w -> rows i0 = w*16, all 64 cols.
    const int i0 = w * 16;
    const uint32_t xBase = (uint32_t)__cvta_generic_to_shared(Xh);
    const uint32_t rBase = (uint32_t)__cvta_generic_to_shared(Rh);
    float cacc[8][4];
#pragma unroll
    for (int t = 0; t < 8; t++)
#pragma unroll
        for (int e = 0; e < 4; e++) cacc[t][e] = 0.f;

    for (int k = 0; k < 8; k++) {
        const int k0 = k * 16;
        uint32_t a0, a1, a2, a3;
        {
            uint32_t aaddr = xBase +
                (((i0 + (lane & 15)) * STH + k0 + ((lane >> 4) << 3)) << 1);
            asm volatile(
                "ldmatrix.sync.aligned.m8n8.x4.shared.b16 {%0,%1,%2,%3}, [%4];"
                : "=r"(a0), "=r"(a1), "=r"(a2), "=r"(a3) : "r"(aaddr));
        }
#pragma unroll
        for (int p = 0; p < 4; p++) {
            const int j0 = p * 16;
            uint32_t b0, b1, b2, b3;
            uint32_t row = j0 + (lane & 7) + ((lane >> 4) << 3);
            uint32_t col = k0 + (((lane >> 3) & 1) << 3);
            uint32_t baddr = rBase + ((row * STH + col) << 1);
            asm volatile(
                "ldmatrix.sync.aligned.m8n8.x4.shared.b16 {%0,%1,%2,%3}, [%4];"
                : "=r"(b0), "=r"(b1), "=r"(b2), "=r"(b3) : "r"(baddr));
            asm volatile(
                "mma.sync.aligned.m16n8k16.row.col.f32.f16.f16.f32 "
                "{%0,%1,%2,%3}, {%4,%5,%6,%7}, {%8,%9}, {%0,%1,%2,%3};"
                : "+f"(cacc[2 * p][0]), "+f"(cacc[2 * p][1]),
                  "+f"(cacc[2 * p][2]), "+f"(cacc[2 * p][3])
                : "r"(a0), "r"(a1), "r"(a2), "r"(a3), "r"(b0), "r"(b1));
            asm volatile(
                "mma.sync.aligned.m16n8k16.row.col.f32.f16.f16.f32 "
                "{%0,%1,%2,%3}, {%4,%5,%6,%7}, {%8,%9}, {%0,%1,%2,%3};"
                : "+f"(cacc[2 * p + 1][0]), "+f"(cacc[2 * p + 1][1]),
                  "+f"(cacc[2 * p + 1][2]), "+f"(cacc[2 * p + 1][3])
                : "r"(a0), "r"(a1), "r"(a2), "r"(a3), "r"(b2), "r"(b3));
        }
    }

    // Per-row argmax/argmin with top-2 tracking; rows r0, r1 sequentially.
#pragma unroll
    for (int half = 0; half < 2; half++) {
        const int r = i0 + (lane >> 2) + half * 8;
        float bm1 = -3.4e38f, bm2 = -3.4e38f; int bi1 = 9999;
        float sm1 =  3.4e38f, sm2 =  3.4e38f; int si1 = 9999;
#pragma unroll
        for (int t = 0; t < 8; t++) {
            const int hcol = t * 8 + (lane & 3) * 2;
#pragma unroll
            for (int e = 0; e < 2; e++) {
                float v = cacc[t][half * 2 + e];
                int   h = hcol + e;
                if (v > bm1) { bm2 = bm1; bm1 = v; bi1 = h; }
                else bm2 = fmaxf(bm2, v);
                if (v < sm1) { sm2 = sm1; sm1 = v; si1 = h; }
                else sm2 = fminf(sm2, v);
            }
        }
        // reduce across the 4 lanes sharing this row (xor 1, 2)
#pragma unroll
        for (int off = 1; off <= 2; off <<= 1) {
            float obm1 = __shfl_xor_sync(0xffffffffu, bm1, off);
            int   obi1 = __shfl_xor_sync(0xffffffffu, bi1, off);
            float obm2 = __shfl_xor_sync(0xffffffffu, bm2, off);
            float osm1 = __shfl_xor_sync(0xffffffffu, sm1, off);
            int   osi1 = __shfl_xor_sync(0xffffffffu, si1, off);
            float osm2 = __shfl_xor_sync(0xffffffffu, sm2, off);
            if (obm1 > bm1 || (obm1 == bm1 && obi1 < bi1)) {
                bm2 = fmaxf(bm1, obm2); bm1 = obm1; bi1 = obi1;
            } else bm2 = fmaxf(bm2, obm1);
            if (osm1 < sm1 || (osm1 == sm1 && osi1 < si1)) {
                sm2 = fminf(sm1, osm2); sm1 = osm1; si1 = osi1;
            } else sm2 = fminf(sm2, osm1);
        }
        if ((lane & 3) == 0) {
            const float gapb = bm1 - bm2;
            const float gapm = sm2 - sm1;
            const float marg = fabsf(bm1 + sm1);   // |bv - (-mv)|
            const int n = n0 + r;
            if (gapb > PROJ_TH && gapm > PROJ_TH && marg > PROJ_TH) {
                int idx = (bm1 >= -sm1) ? bi1 : (HB + si1);
                int m = msk[(size_t)b * NN + n];
                g_key[(size_t)b * NN + n] = idx + (m ? 0 : (NBINS - 1));
            } else {
                int pos = atomicAdd(scnt, 1);
                slist[pos] = r;
            }
        }
    }
    __syncthreads();

    // Exact fp32 recompute for flagged nodes (one warp per node).
    const int cnt = *scnt;
    for (int ii = w; ii < cnt; ii += 8) {
        const int r = slist[ii];
        const int h0 = lane;
        const int h1 = lane + 32;
        const bool v1ok = (h1 < HB);
        float d0 = 0.f, d1 = 0.f;
        const float4* xr4 = (const float4*)(x_msg + ((size_t)b * NN + n0 + r) * FM);
        for (int f4 = 0; f4 < FM / 4; f4++) {
            float4 xv = __ldg(xr4 + f4);
            const float* rp = rot + (4 * f4) * ROTC;
            d0 = fmaf(xv.x, __ldg(rp + h0), d0);
            d0 = fmaf(xv.y, __ldg(rp + ROTC + h0), d0);
            d0 = fmaf(xv.z, __ldg(rp + 2 * ROTC + h0), d0);
            d0 = fmaf(xv.w, __ldg(rp + 3 * ROTC + h0), d0);
            if (v1ok) {
                d1 = fmaf(xv.x, __ldg(rp + h1), d1);
                d1 = fmaf(xv.y, __ldg(rp + ROTC + h1), d1);
                d1 = fmaf(xv.z, __ldg(rp + 2 * ROTC + h1), d1);
                d1 = fmaf(xv.w, __ldg(rp + 3 * ROTC + h1), d1);
            }
        }
        float bv = d0; int bh = h0;
        if (v1ok && d1 > bv) { bv = d1; bh = h1; }
        float mv = d0; int mh = h0;
        if (v1ok && d1 < mv) { mv = d1; mh = h1; }
#pragma unroll
        for (int off = 16; off; off >>= 1) {
            float obv = __shfl_xor_sync(0xffffffffu, bv, off);
            int   obh = __shfl_xor_sync(0xffffffffu, bh, off);
            float omv = __shfl_xor_sync(0xffffffffu, mv, off);
            int   omh = __shfl_xor_sync(0xffffffffu, mh, off);
            if (obv > bv || (obv == bv && obh < bh)) { bv = obv; bh = obh; }
            if (omv < mv || (omv == mv && omh < mh)) { mv = omv; mh = omh; }
        }
        if (lane == 0) {
            const int n = n0 + r;
            int idx = (bv >= -mv) ? bh : (HB + mh);
            int m = msk[(size_t)b * NN + n];
            g_key[(size_t)b * NN + n] = idx + (m ? 0 : (NBINS - 1));
        }
    }
}

// ---------------------------------------------------------------------------
// K2: stable counting sort per batch (unchanged).
// ---------------------------------------------------------------------------
__global__ void k_sort(const int* __restrict__ msk,
                       float* __restrict__ out) {
    const int b = blockIdx.x;
    extern __shared__ unsigned short off[];        // [NKEYS][128]
    __shared__ unsigned int keyTotal[NKEYS];
    __shared__ unsigned int keyBase[NKEYS];
    const int t = threadIdx.x;

    for (int i = t; i < NKEYS * 128; i += 128) off[i] = 0;
    __syncthreads();

    const int* kb = g_key + (size_t)b * NN;
    const int base_n = t * 100;
    for (int q = 0; q < 100; q++) {
        int k = kb[base_n + q];
        off[k * 128 + t]++;
    }
    __syncthreads();

    for (int k = t; k < NKEYS; k += 128) {
        unsigned int run = 0;
        for (int tt = 0; tt < 128; tt++) {
            unsigned short c = off[k * 128 + tt];
            off[k * 128 + tt] = (unsigned short)run;
            run += c;
        }
        keyTotal[k] = run;
    }
    __syncthreads();
    if (t == 0) {
        unsigned int run = 0;
        for (int k = 0; k < NKEYS; k++) { keyBase[k] = run; run += keyTotal[k]; }
    }
    __syncthreads();

    int* gb = g_bins + (size_t)b * NN;
    const int* mb = msk + (size_t)b * NN;
    float* out_bins = out + OFF_BINS + (size_t)b * NN;
    float* out_mskf = out + OFF_MSKF + (size_t)b * NN;
    for (int q = 0; q < 100; q++) {
        int n = base_n + q;
        int k = kb[n];
        unsigned int pos = keyBase[k] + off[k * 128 + t];
        off[k * 128 + t]++;
        gb[pos] = n;
        out_bins[pos] = (float)n;
        out_mskf[pos] = mb[n] ? 1.0f : 0.0f;
    }
}

// ---------------------------------------------------------------------------
// K4: per-bin gaussian kernel via tensor-core mma.sync + fused x_node gather.
// v2 (kept from R16: mildly positive): batched staging loads (MLP 8), 2-row
// batched gather with streaming ld/st, streaming dm writes.
// 512 thr x occ 2 = 32 warps/SM (hardware warp max).
// ---------------------------------------------------------------------------
__global__ void __launch_bounds__(512, 2)
k_dm(const float4* __restrict__ x_msg4,
     const int* __restrict__ msk,
     const float4* __restrict__ x_node4,
     float* __restrict__ out) {
    const int b   = blockIdx.x / NBINS;
    const int bin = blockIdx.x % NBINS;
    extern __shared__ char smraw[];
    __half* As = (__half*)smraw;                       // [128][STH]
    float* na  = (float*)(smraw + 128 * STH * 2);      // [128]
    float* mm  = na + 128;                             // [128]
    const int tid  = threadIdx.x;        // 512
    const int w    = tid >> 5;           // 0..15
    const int lane = tid & 31;

    const int* gb = g_bins + ((size_t)b * NBINS + bin) * BS;
    const float4* xb = x_msg4 + (size_t)b * NN * (FM / 4);

    // Staging with batched loads: issue all 8 row loads first (MLP 8).
    {
        float4 vv[8];
        float  mk[8];
#pragma unroll
        for (int rr = 0; rr < 8; rr++) {
            const int r = w * 8 + rr;
            const int src = gb[r];                    // warp-uniform broadcast
            mk[rr] = msk[(size_t)b * NN + src] ? 1.f : 0.f;
            vv[rr] = xb[(size_t)src * (FM / 4) + lane];
        }
#pragma unroll
        for (int rr = 0; rr < 8; rr++) {
            const int r = w * 8 + rr;
            const float m = mk[rr];
            float4 v = vv[rr];
            v.x *= m; v.y *= m; v.z *= m; v.w *= m;
            __half2 h0 = __floats2half2_rn(v.x, v.y);
            __half2 h1 = __floats2half2_rn(v.z, v.w);
            *(__half2*)(As + r * STH + lane * 4)     = h0;
            *(__half2*)(As + r * STH + lane * 4 + 2) = h1;
            float2 f0 = __half22float2(h0), f1 = __half22float2(h1);
            float s = f0.x * f0.x + f0.y * f0.y + f1.x * f1.x + f1.y * f1.y;
#pragma unroll
            for (int o = 16; o; o >>= 1) s += __shfl_xor_sync(0xffffffffu, s, o);
            if (lane == 0) { na[r] = s; mm[r] = m; }
        }
    }
    __syncthreads();

    const int i0  = (w & 7) * 16;
    const int j0c = (w >> 3) * 64;
    const uint32_t asBase = (uint32_t)__cvta_generic_to_shared(As);

    float cacc[8][4];
#pragma unroll
    for (int t = 0; t < 8; t++)
#pragma unroll
        for (int e = 0; e < 4; e++) cacc[t][e] = 0.f;

    for (int k = 0; k < 8; k++) {
        const int k0 = k * 16;
        uint32_t a0, a1, a2, a3;
        {
            uint32_t aaddr = asBase +
                (((i0 + (lane & 15)) * STH + k0 + ((lane >> 4) << 3)) << 1);
            asm volatile(
                "ldmatrix.sync.aligned.m8n8.x4.shared.b16 {%0,%1,%2,%3}, [%4];"
                : "=r"(a0), "=r"(a1), "=r"(a2), "=r"(a3) : "r"(aaddr));
        }
#pragma unroll
        for (int p = 0; p < 4; p++) {
            const int j0 = j0c + p * 16;
            uint32_t b0, b1, b2, b3;
            uint32_t row = j0 + (lane & 7) + ((lane >> 4) << 3);
            uint32_t col = k0 + (((lane >> 3) & 1) << 3);
            uint32_t baddr = asBase + ((row * STH + col) << 1);
            asm volatile(
                "ldmatrix.sync.aligned.m8n8.x4.shared.b16 {%0,%1,%2,%3}, [%4];"
                : "=r"(b0), "=r"(b1), "=r"(b2), "=r"(b3) : "r"(baddr));
            asm volatile(
                "mma.sync.aligned.m16n8k16.row.col.f32.f16.f16.f32 "
                "{%0,%1,%2,%3}, {%4,%5,%6,%7}, {%8,%9}, {%0,%1,%2,%3};"
                : "+f"(cacc[2 * p][0]), "+f"(cacc[2 * p][1]),
                  "+f"(cacc[2 * p][2]), "+f"(cacc[2 * p][3])
                : "r"(a0), "r"(a1), "r"(a2), "r"(a3), "r"(b0), "r"(b1));
            asm volatile(
                "mma.sync.aligned.m16n8k16.row.col.f32.f16.f16.f32 "
                "{%0,%1,%2,%3}, {%4,%5,%6,%7}, {%8,%9}, {%0,%1,%2,%3};"
                : "+f"(cacc[2 * p + 1][0]), "+f"(cacc[2 * p + 1][1]),
                  "+f"(cacc[2 * p + 1][2]), "+f"(cacc[2 * p + 1][3])
                : "r"(a0), "r"(a1), "r"(a2), "r"(a3), "r"(b2), "r"(b3));
        }
    }

    {
        float* dout = out + OFF_DM + (size_t)blockIdx.x * BS * BS;
        const float cst = -0.14426950408889634f;   // -DIST_MULT * log2(e)
        const int r0 = i0 + (lane >> 2);
        const int r1 = r0 + 8;
        const float na0 = na[r0], m0 = mm[r0];
        const float na1 = na[r1], m1 = mm[r1];
#pragma unroll
        for (int t = 0; t < 8; t++) {
            const int j = j0c + t * 8 + (lane & 3) * 2;
            const float naj0 = na[j], mj0 = mm[j];
            const float naj1 = na[j + 1], mj1 = mm[j + 1];
            float x, d;
            x = fmaxf(na0 + naj0 - 2.0f * cacc[t][0], 1e-6f);
            d = fminf(ex2f(cst * (x * rsqf(x))) * m0 * mj0, 1.0f);
            float e0 = d;
            x = fmaxf(na0 + naj1 - 2.0f * cacc[t][1], 1e-6f);
            d = fminf(ex2f(cst * (x * rsqf(x))) * m0 * mj1, 1.0f);
            float e1 = d;
            x = fmaxf(na1 + naj0 - 2.0f * cacc[t][2], 1e-6f);
            d = fminf(ex2f(cst * (x * rsqf(x))) * m1 * mj0, 1.0f);
            float e2 = d;
            x = fmaxf(na1 + naj1 - 2.0f * cacc[t][3], 1e-6f);
            d = fminf(ex2f(cst * (x * rsqf(x))) * m1 * mj1, 1.0f);
            float e3 = d;
            __stcs((float2*)(dout + (size_t)r0 * BS + j), make_float2(e0, e1));
            __stcs((float2*)(dout + (size_t)r1 * BS + j), make_float2(e2, e3));
        }
    }

    // Fused x_node gather: 2-row batches, streaming ld/st (4 float4 in flight).
    const float4* xn = x_node4 + (size_t)b * NN * (FN / 4);
    float4* xo = (float4*)(out + OFF_XNODE) + (size_t)blockIdx.x * BS * (FN / 4);
#pragma unroll
    for (int it = 0; it < 4; it++) {
        const int r0 = w + it * 32;
        const int r1 = r0 + 16;
        const int s0 = gb[r0];
        const int s1 = gb[r1];
        float4 a0 = __ldcs(xn + (size_t)s0 * 64 + lane);
        float4 a1 = __ldcs(xn + (size_t)s0 * 64 + lane + 32);
        float4 b0 = __ldcs(xn + (size_t)s1 * 64 + lane);
        float4 b1 = __ldcs(xn + (size_t)s1 * 64 + lane + 32);
        __stcs(xo + (size_t)r0 * 64 + lane,      a0);
        __stcs(xo + (size_t)r0 * 64 + lane + 32, a1);
        __stcs(xo + (size_t)r1 * 64 + lane,      b0);
        __stcs(xo + (size_t)r1 * 64 + lane + 32, b1);
    }
}

// ---------------------------------------------------------------------------
extern "C" void kernel_launch(void* const* d_in, const int* in_sizes, int n_in,
                              void* d_out, int out_size) {
    const float* x_msg  = (const float*)d_in[0];
    const float* x_node = (const float*)d_in[1];
    const int*   msk    = (const int*)d_in[2];
    const float* rot    = (const float*)d_in[3];
    float* out = (float*)d_out;

    const int SM1 = 128 * STH * 2 + 64 * STH * 2 + 4 + 128 * 4;  // 52740
    const int SM2 = NKEYS * 128 * 2;                    // 51200
    const int SM4 = 128 * STH * 2 + 2 * 128 * 4;        // 35840
    cudaFuncSetAttribute(k_proj, cudaFuncAttributeMaxDynamicSharedMemorySize, SM1);
    cudaFuncSetAttribute(k_sort, cudaFuncAttributeMaxDynamicSharedMemorySize, SM2);
    cudaFuncSetAttribute(k_dm,   cudaFuncAttributeMaxDynamicSharedMemorySize, SM4);

    k_proj<<<BB * (NN / 128), 256, SM1>>>(x_msg, msk, rot);
    k_sort<<<BB, 128, SM2>>>(msk, out);
    k_dm<<<BB * NBINS, 512, SM4>>>((const float4*)x_msg, msk,
                                   (const float4*)x_node, out);
}